// round 11
// baseline (speedup 1.0000x reference)
#include <cuda_runtime.h>
#include <cuda_bf16.h>
#include <cstdint>

#define TOKENS  16384
#define DINNER  2048
#define DSTATE  512
#define TOTAL   (TOKENS * DSTATE)

// ---------------------------------------------------------------------------
// Device-global scratch (no allocation allowed in kernel_launch)
// ---------------------------------------------------------------------------
__device__ float g_noise_scale;
__device__ float g_pred[TOTAL];                         // tanh(X @ W)
__device__ float g_noise[5u * TOTAL];                   // raw normals, [s][idx]
__device__ __nv_bfloat16 g_Ahi[TOKENS * DINNER];        // A split hi   [m][k]
__device__ __nv_bfloat16 g_Alo[TOKENS * DINNER];        // A split lo   [m][k]
__device__ __nv_bfloat16 g_Whi[DSTATE * DINNER];        // W^T split hi [n][k]
__device__ __nv_bfloat16 g_Wlo[DSTATE * DINNER];        // W^T split lo [n][k]

// ---------------------------------------------------------------------------
// Helpers
// ---------------------------------------------------------------------------
__device__ __forceinline__ uint32_t smem_u32(const void* p) {
    uint32_t a;
    asm("{ .reg .u64 t; cvta.to.shared.u64 t, %1; cvt.u32.u64 %0, t; }" : "=r"(a) : "l"(p));
    return a;
}

__device__ __forceinline__ uint32_t sw128(uint32_t o) { return o ^ ((o >> 3) & 0x70); }

__device__ __forceinline__ void cpa16(uint32_t s, const void* g) {
    asm volatile("cp.async.cg.shared.global [%0], [%1], 16;" :: "r"(s), "l"(g));
}

__device__ __forceinline__ void ldm_x4(uint32_t* d, uint32_t addr) {
    asm volatile("ldmatrix.sync.aligned.m8n8.x4.shared.b16 {%0,%1,%2,%3}, [%4];"
                 : "=r"(d[0]), "=r"(d[1]), "=r"(d[2]), "=r"(d[3]) : "r"(addr));
}

__device__ __forceinline__ void mma_bf16(float* c, const uint32_t* a, const uint32_t* b) {
    asm volatile("mma.sync.aligned.m16n8k16.row.col.f32.bf16.bf16.f32 "
                 "{%0,%1,%2,%3}, {%4,%5,%6,%7}, {%8,%9}, {%0,%1,%2,%3};"
                 : "+f"(c[0]), "+f"(c[1]), "+f"(c[2]), "+f"(c[3])
                 : "r"(a[0]), "r"(a[1]), "r"(a[2]), "r"(a[3]), "r"(b[0]), "r"(b[1]));
}

// Fast tanh via MUFU exp: abs err ~1e-7.
__device__ __forceinline__ float fast_tanh(float x) {
    float e = __expf(2.0f * x);
    return 1.0f - __fdividef(2.0f, e + 1.0f);
}

// ---------------------------------------------------------------------------
// Threefry-2x32 (JAX-compatible, 20 rounds)
// ---------------------------------------------------------------------------
__host__ __device__ __forceinline__ uint32_t rotl32(uint32_t x, int r) {
    return (x << r) | (x >> (32 - r));
}

__host__ __device__ __forceinline__ void threefry2x32(uint32_t k0, uint32_t k1,
                                                      uint32_t& x0, uint32_t& x1) {
    uint32_t k2 = k0 ^ k1 ^ 0x1BD11BDAu;
    x0 += k0; x1 += k1;
#define TF_R(r) { x0 += x1; x1 = rotl32(x1, (r)); x1 ^= x0; }
    TF_R(13) TF_R(15) TF_R(26) TF_R(6)
    x0 += k1; x1 += k2 + 1u;
    TF_R(17) TF_R(29) TF_R(16) TF_R(24)
    x0 += k2; x1 += k0 + 2u;
    TF_R(13) TF_R(15) TF_R(26) TF_R(6)
    x0 += k0; x1 += k1 + 3u;
    TF_R(17) TF_R(29) TF_R(16) TF_R(24)
    x0 += k1; x1 += k2 + 4u;
    TF_R(13) TF_R(15) TF_R(26) TF_R(6)
    x0 += k2; x1 += k0 + 5u;
#undef TF_R
}

// ---------------------------------------------------------------------------
// XLA ErfInv32 (MUFU log) + JAX bits->normal
// ---------------------------------------------------------------------------
__device__ __forceinline__ float erfinv_fast(float x) {
    float w = -__logf(1.0f - x * x);
    float p;
    if (w < 5.0f) {
        w = w - 2.5f;
        p = 2.81022636e-08f;
        p = fmaf(p, w, 3.43273939e-07f);
        p = fmaf(p, w, -3.5233877e-06f);
        p = fmaf(p, w, -4.39150654e-06f);
        p = fmaf(p, w, 0.00021858087f);
        p = fmaf(p, w, -0.00125372503f);
        p = fmaf(p, w, -0.00417768164f);
        p = fmaf(p, w, 0.246640727f);
        p = fmaf(p, w, 1.50140941f);
    } else {
        w = sqrtf(w) - 3.0f;
        p = -0.000200214257f;
        p = fmaf(p, w, 0.000100950558f);
        p = fmaf(p, w, 0.00134934322f);
        p = fmaf(p, w, -0.00367342844f);
        p = fmaf(p, w, 0.00573950773f);
        p = fmaf(p, w, -0.0076224613f);
        p = fmaf(p, w, 0.00943887047f);
        p = fmaf(p, w, 1.00167406f);
        p = fmaf(p, w, 2.83297682f);
    }
    return p * x;
}

__device__ __forceinline__ float bits_to_normal(uint32_t bits) {
    float f = __uint_as_float((bits >> 9) | 0x3f800000u) - 1.0f;
    const float lo = -0.99999994f;
    float u = fmaxf(lo, fmaf(f, 2.0f, lo));
    return 1.41421356f * erfinv_fast(u);
}

// ---------------------------------------------------------------------------
// Kernel: noise scale reduction
// ---------------------------------------------------------------------------
__global__ void reduce_noise_scale(const float* __restrict__ s) {
    __shared__ float ws[32];
    int t = threadIdx.x;
    float4 a = *(const float4*)(s + t * 4);
    float4 b = *(const float4*)(s + 4096 + t * 4);
    float4 c = *(const float4*)(s + 8192 + t * 4);
    float4 d = *(const float4*)(s + 12288 + t * 4);
    float v[16] = {a.x,a.y,a.z,a.w, b.x,b.y,b.z,b.w, c.x,c.y,c.z,c.w, d.x,d.y,d.z,d.w};
    float sum = 0.0f;
#pragma unroll
    for (int i = 0; i < 16; i++) sum += 1.0f / (1.0f + expf(-v[i]));
#pragma unroll
    for (int o = 16; o; o >>= 1) sum += __shfl_xor_sync(0xffffffffu, sum, o);
    if ((t & 31) == 0) ws[t >> 5] = sum;
    __syncthreads();
    if (t < 32) {
        float x = ws[t];
#pragma unroll
        for (int o = 16; o; o >>= 1) x += __shfl_xor_sync(0xffffffffu, x, o);
        if (t == 0) {
            float mean_sig = x / (float)TOKENS;
            g_noise_scale = sqrtf(2.0f * 0.1f * (1.0f + mean_sig * 5.0f));
        }
    }
}

// ---------------------------------------------------------------------------
// Kernel: standalone noise generation — sized to CO-RESIDE with the GEMM.
// GEMM leaves ~10.2K regs free per SM (256 x 216 used). This CTA needs
// 128 x 56 = 7.2K regs, 0 smem -> fits. Pure ALU/FMA work fills the ~80%
// of issue slots the tensor-bound GEMM leaves idle.
// ---------------------------------------------------------------------------
struct FoldedKeys { uint32_t k[10]; };

__global__ __launch_bounds__(128, 9) void noise_kernel(FoldedKeys keys) {
    uint32_t base = (uint32_t)(blockIdx.x * 128 + threadIdx.x) * 4;
#pragma unroll
    for (int s = 0; s < 5; s++) {
        uint32_t k0 = keys.k[2 * s];
        uint32_t k1 = keys.k[2 * s + 1];
        float nv[4];
#pragma unroll
        for (int c = 0; c < 4; c++) {
            uint32_t x0 = 0u, x1 = base + (uint32_t)c;
            threefry2x32(k0, k1, x0, x1);
            nv[c] = bits_to_normal(x0 ^ x1);
        }
        float4 o4 = {nv[0], nv[1], nv[2], nv[3]};
        *(float4*)(g_noise + (size_t)s * TOTAL + base) = o4;
    }
}

// ---------------------------------------------------------------------------
// Kernel: split A (fp32 -> bf16 hi/lo)
// ---------------------------------------------------------------------------
__device__ __forceinline__ uint32_t pk_bf16(__nv_bfloat16 a, __nv_bfloat16 b) {
    __nv_bfloat162 t(a, b);
    return *reinterpret_cast<uint32_t*>(&t);
}

__global__ __launch_bounds__(256) void split_A(const float* __restrict__ A) {
    size_t i = ((size_t)blockIdx.x * 256 + threadIdx.x) * 4;
    float4 v = *(const float4*)(A + i);
    __nv_bfloat16 h0 = __float2bfloat16(v.x), h1 = __float2bfloat16(v.y);
    __nv_bfloat16 h2 = __float2bfloat16(v.z), h3 = __float2bfloat16(v.w);
    __nv_bfloat16 l0 = __float2bfloat16(v.x - __bfloat162float(h0));
    __nv_bfloat16 l1 = __float2bfloat16(v.y - __bfloat162float(h1));
    __nv_bfloat16 l2 = __float2bfloat16(v.z - __bfloat162float(h2));
    __nv_bfloat16 l3 = __float2bfloat16(v.w - __bfloat162float(h3));
    uint2 uh = { pk_bf16(h0, h1), pk_bf16(h2, h3) };
    uint2 ul = { pk_bf16(l0, l1), pk_bf16(l2, l3) };
    *(uint2*)(g_Ahi + i) = uh;
    *(uint2*)(g_Alo + i) = ul;
}

// ---------------------------------------------------------------------------
// Kernel: split + transpose W  ([K,N] fp32 -> [N,K] bf16 hi/lo)
// ---------------------------------------------------------------------------
__global__ __launch_bounds__(256) void split_W(const float* __restrict__ W) {
    __shared__ float t[64][33];
    int n0 = blockIdx.x * 32, k0 = blockIdx.y * 64;
    int tid = threadIdx.x;
#pragma unroll
    for (int j = 0; j < 8; j++) {
        int idx = tid + j * 256;
        int kr = idx >> 5, nc = idx & 31;
        t[kr][nc] = W[(size_t)(k0 + kr) * DSTATE + n0 + nc];
    }
    __syncthreads();
    int n = tid >> 3, kg = tid & 7;
    uint32_t hi[4], lo[4];
#pragma unroll
    for (int e = 0; e < 8; e += 2) {
        float a = t[kg * 8 + e][n], b = t[kg * 8 + e + 1][n];
        __nv_bfloat16 ha = __float2bfloat16(a), hb = __float2bfloat16(b);
        __nv_bfloat16 la = __float2bfloat16(a - __bfloat162float(ha));
        __nv_bfloat16 lb = __float2bfloat16(b - __bfloat162float(hb));
        hi[e >> 1] = pk_bf16(ha, hb);
        lo[e >> 1] = pk_bf16(la, lb);
    }
    size_t off = (size_t)(n0 + n) * DINNER + k0 + kg * 8;
    *(uint4*)(g_Whi + off) = make_uint4(hi[0], hi[1], hi[2], hi[3]);
    *(uint4*)(g_Wlo + off) = make_uint4(lo[0], lo[1], lo[2], lo[3]);
}

// ---------------------------------------------------------------------------
// Kernel: bf16x3 GEMM via mma.sync (HMMA) + tanh epilogue -> g_pred
// Proven R6 shape: 256 threads, 8 warps 2(M)x4(N), warp tile 64x32,
// CTA tile 128x128x64, 3-stage cp.async, SW128 smem, ldmatrix everything.
// ---------------------------------------------------------------------------
#define BK 64
#define STAGE_BYTES (64 * 1024)          // Ahi 16K | Alo 16K | Bhi 16K | Blo 16K
#define GEMM_SMEM   (3 * STAGE_BYTES)
#define NCHUNKS     (DINNER / BK)        // 32
#define OFF_ALO 16384
#define OFF_BHI 32768
#define OFF_BLO 49152

__global__ __launch_bounds__(256, 1) void gemm_bf16x3() {
    extern __shared__ char smem[];
    uint32_t sb = smem_u32(smem);
    const int tid = threadIdx.x;
    const int wid = tid >> 5, lid = tid & 31;
    const int bm = blockIdx.y << 7;
    const int bn = blockIdx.x << 7;

    const int wm = (wid & 1) * 64;
    const int wn = (wid >> 1) * 32;

    int goffA[4], goffB[4]; uint32_t soff[4];
#pragma unroll
    for (int i = 0; i < 4; i++) {
        int u = tid + i * 256;
        int r = u >> 3, cu = u & 7;
        goffA[i] = (bm + r) * DINNER + cu * 8;
        goffB[i] = (bn + r) * DINNER + cu * 8;
        soff[i]  = sw128((uint32_t)(r * 128 + cu * 16));
    }

    auto load_chunk = [&](int c, int s) {
        uint32_t st = sb + s * STAGE_BYTES;
        int k0 = c * BK;
#pragma unroll
        for (int i = 0; i < 4; i++) {
            cpa16(st +           soff[i], g_Ahi + goffA[i] + k0);
            cpa16(st + OFF_ALO + soff[i], g_Alo + goffA[i] + k0);
            cpa16(st + OFF_BHI + soff[i], g_Whi + goffB[i] + k0);
            cpa16(st + OFF_BLO + soff[i], g_Wlo + goffB[i] + k0);
        }
        asm volatile("cp.async.commit_group;" ::: "memory");
    };

    float acc[4][4][4];
#pragma unroll
    for (int m = 0; m < 4; m++)
#pragma unroll
        for (int n = 0; n < 4; n++)
#pragma unroll
            for (int j = 0; j < 4; j++) acc[m][n][j] = 0.0f;

    load_chunk(0, 0);
    load_chunk(1, 1);

    const uint32_t a_rb = (uint32_t)(wm + (lid & 15)) * 128;
    const uint32_t a_xm = (uint32_t)((lid & 7) << 4);
    const uint32_t a_kb = (uint32_t)((lid >> 4) * 16);

    const uint32_t b_m  = (uint32_t)(lid >> 3);
    const uint32_t b_r  = (uint32_t)(lid & 7);
    const uint32_t b_xm = b_r << 4;
    const uint32_t b_kb = (b_m & 1) * 16;
    uint32_t b_rb[2];
#pragma unroll
    for (int j = 0; j < 2; j++)
        b_rb[j] = (uint32_t)(wn + (2 * j + (int)(b_m >> 1)) * 8 + (int)b_r) * 128;

    for (int c = 0; c < NCHUNKS; c++) {
        int s = c % 3;
        if (c + 2 < NCHUNKS) load_chunk(c + 2, (c + 2) % 3);

        if (c + 2 < NCHUNKS)      asm volatile("cp.async.wait_group 2;" ::: "memory");
        else if (c + 1 < NCHUNKS) asm volatile("cp.async.wait_group 1;" ::: "memory");
        else                      asm volatile("cp.async.wait_group 0;" ::: "memory");
        __syncthreads();

        uint32_t st = sb + s * STAGE_BYTES;
#pragma unroll
        for (int kk = 0; kk < 4; kk++) {
            uint32_t ah[4][4], al[4][4];
#pragma unroll
            for (int t = 0; t < 4; t++) {
                uint32_t off = a_rb + (uint32_t)(t * 16 * 128)
                             + (((uint32_t)(kk * 32) + a_kb) ^ a_xm);
                ldm_x4(ah[t], st + off);
                ldm_x4(al[t], st + OFF_ALO + off);
            }
            uint32_t bh[4][2], bl[4][2];
#pragma unroll
            for (int j = 0; j < 2; j++) {
                uint32_t off = b_rb[j] + (((uint32_t)(kk * 32) + b_kb) ^ b_xm);
                uint32_t dh[4], dl[4];
                ldm_x4(dh, st + OFF_BHI + off);
                ldm_x4(dl, st + OFF_BLO + off);
                bh[2*j][0] = dh[0]; bh[2*j][1] = dh[1];
                bh[2*j+1][0] = dh[2]; bh[2*j+1][1] = dh[3];
                bl[2*j][0] = dl[0]; bl[2*j][1] = dl[1];
                bl[2*j+1][0] = dl[2]; bl[2*j+1][1] = dl[3];
            }
#pragma unroll
            for (int m = 0; m < 4; m++)
#pragma unroll
                for (int n = 0; n < 4; n++) {
                    mma_bf16(acc[m][n], ah[m], bh[n]);
                    mma_bf16(acc[m][n], ah[m], bl[n]);
                    mma_bf16(acc[m][n], al[m], bh[n]);
                }
        }
        __syncthreads();
    }

    const int r0 = bm + wm + (lid >> 2);
    const int c0 = bn + wn + (lid & 3) * 2;
#pragma unroll
    for (int m = 0; m < 4; m++) {
#pragma unroll
        for (int n = 0; n < 4; n++) {
            float2 lo2 = { fast_tanh(acc[m][n][0]), fast_tanh(acc[m][n][1]) };
            float2 hi2 = { fast_tanh(acc[m][n][2]), fast_tanh(acc[m][n][3]) };
            int row = r0 + m * 16;
            int col = c0 + n * 8;
            *(float2*)(g_pred + (size_t)row * DSTATE + col)       = lo2;
            *(float2*)(g_pred + (size_t)(row + 8) * DSTATE + col) = hi2;
        }
    }
}

// ---------------------------------------------------------------------------
// Kernel: light 5-step Langevin update (noise precomputed) -> d_out
// ---------------------------------------------------------------------------
__global__ __launch_bounds__(256) void step_kernel(const float* __restrict__ h_init,
                                                   float* __restrict__ out) {
    int t = blockIdx.x * blockDim.x + threadIdx.x;
    int base = t * 4;

    float4 h4 = *(const float4*)(h_init + base);
    float4 p4 = *(const float4*)(g_pred + base);
    const float scale = g_noise_scale;

    float hv[4] = {h4.x, h4.y, h4.z, h4.w};
    float pv[4] = {p4.x, p4.y, p4.z, p4.w};

#pragma unroll
    for (int s = 0; s < 5; s++) {
        float4 nz = *(const float4*)(g_noise + (size_t)s * TOTAL + base);
        float nv[4] = {nz.x, nz.y, nz.z, nz.w};
#pragma unroll
        for (int c = 0; c < 4; c++) {
            float hh = hv[c];
            hv[c] = fast_tanh(hh - (hh - pv[c]) * 0.1f + nv[c] * scale);
        }
    }

    float4 o4 = {hv[0], hv[1], hv[2], hv[3]};
    *(float4*)(out + base) = o4;
}

// ---------------------------------------------------------------------------
// Launch: fork side stream (reduce + noise) to co-run with splits + GEMM.
// ---------------------------------------------------------------------------
extern "C" void kernel_launch(void* const* d_in, const int* in_sizes, int n_in,
                              void* d_out, int out_size) {
    const float* h_init   = (const float*)d_in[0];
    const float* x_ctx    = (const float*)d_in[1];
    const float* surprise = (const float*)d_in[2];
    const float* weight   = (const float*)d_in[3];
    float* out = (float*)d_out;

    FoldedKeys keys;
    for (int i = 0; i < 5; i++) {
        uint32_t x0 = 0u, x1 = (uint32_t)i;
        threefry2x32(0u, 42u, x0, x1);
        keys.k[2 * i]     = x0;
        keys.k[2 * i + 1] = x1;
    }

    cudaStream_t s2;
    cudaStreamCreateWithFlags(&s2, cudaStreamNonBlocking);
    cudaEvent_t eFork, eJoin;
    cudaEventCreateWithFlags(&eFork, cudaEventDisableTiming);
    cudaEventCreateWithFlags(&eJoin, cudaEventDisableTiming);

    // fork
    cudaEventRecord(eFork, 0);
    cudaStreamWaitEvent(s2, eFork, 0);

    // side stream: reduction + noise generation (56-reg CTAs co-reside w/ GEMM)
    reduce_noise_scale<<<1, 1024, 0, s2>>>(surprise);
    noise_kernel<<<TOTAL / (128 * 4), 128, 0, s2>>>(keys);

    // main stream: splits then GEMM
    split_A<<<(TOKENS * DINNER) / 1024, 256>>>(x_ctx);
    split_W<<<dim3(DSTATE / 32, DINNER / 64), 256>>>(weight);
    cudaFuncSetAttribute(gemm_bf16x3, cudaFuncAttributeMaxDynamicSharedMemorySize, GEMM_SMEM);
    gemm_bf16x3<<<dim3(DSTATE / 128, TOKENS / 128), 256, GEMM_SMEM>>>();

    // join: step needs g_pred + g_noise + g_noise_scale
    cudaEventRecord(eJoin, s2);
    cudaStreamWaitEvent(0, eJoin, 0);
    step_kernel<<<TOTAL / (256 * 4), 256>>>(h_init, out);
}

// round 12
// speedup vs baseline: 1.0468x; 1.0468x over previous
#include <cuda_runtime.h>
#include <cuda_bf16.h>
#include <cstdint>

#define TOKENS  16384
#define DINNER  2048
#define DSTATE  512
#define TOTAL   (TOKENS * DSTATE)

// ---------------------------------------------------------------------------
// Device-global scratch (no allocation allowed in kernel_launch)
// ---------------------------------------------------------------------------
__device__ float g_noise_scale;
__device__ float g_pred[TOTAL];                         // tanh(X @ W)
__device__ __nv_bfloat16 g_Ahi[TOKENS * DINNER];        // A split hi   [m][k]
__device__ __nv_bfloat16 g_Alo[TOKENS * DINNER];        // A split lo   [m][k]
__device__ __nv_bfloat16 g_Whi[DSTATE * DINNER];        // W^T split hi [n][k]
__device__ __nv_bfloat16 g_Wlo[DSTATE * DINNER];        // W^T split lo [n][k]

// ---------------------------------------------------------------------------
// Helpers
// ---------------------------------------------------------------------------
__device__ __forceinline__ uint32_t smem_u32(const void* p) {
    uint32_t a;
    asm("{ .reg .u64 t; cvta.to.shared.u64 t, %1; cvt.u32.u64 %0, t; }" : "=r"(a) : "l"(p));
    return a;
}

__device__ __forceinline__ uint32_t sw128(uint32_t o) { return o ^ ((o >> 3) & 0x70); }

__device__ __forceinline__ void cpa16(uint32_t s, const void* g) {
    asm volatile("cp.async.cg.shared.global [%0], [%1], 16;" :: "r"(s), "l"(g));
}

__device__ __forceinline__ void ldm_x4(uint32_t* d, uint32_t addr) {
    asm volatile("ldmatrix.sync.aligned.m8n8.x4.shared.b16 {%0,%1,%2,%3}, [%4];"
                 : "=r"(d[0]), "=r"(d[1]), "=r"(d[2]), "=r"(d[3]) : "r"(addr));
}

__device__ __forceinline__ void mma_bf16(float* c, const uint32_t* a, const uint32_t* b) {
    asm volatile("mma.sync.aligned.m16n8k16.row.col.f32.bf16.bf16.f32 "
                 "{%0,%1,%2,%3}, {%4,%5,%6,%7}, {%8,%9}, {%0,%1,%2,%3};"
                 : "+f"(c[0]), "+f"(c[1]), "+f"(c[2]), "+f"(c[3])
                 : "r"(a[0]), "r"(a[1]), "r"(a[2]), "r"(a[3]), "r"(b[0]), "r"(b[1]));
}

// Fast tanh via MUFU exp: abs err ~1e-7.
__device__ __forceinline__ float fast_tanh(float x) {
    float e = __expf(2.0f * x);
    return 1.0f - __fdividef(2.0f, e + 1.0f);
}

// ---------------------------------------------------------------------------
// Threefry-2x32 (JAX-compatible, 20 rounds)
// ---------------------------------------------------------------------------
__host__ __device__ __forceinline__ uint32_t rotl32(uint32_t x, int r) {
    return (x << r) | (x >> (32 - r));
}

__host__ __device__ __forceinline__ void threefry2x32(uint32_t k0, uint32_t k1,
                                                      uint32_t& x0, uint32_t& x1) {
    uint32_t k2 = k0 ^ k1 ^ 0x1BD11BDAu;
    x0 += k0; x1 += k1;
#define TF_R(r) { x0 += x1; x1 = rotl32(x1, (r)); x1 ^= x0; }
    TF_R(13) TF_R(15) TF_R(26) TF_R(6)
    x0 += k1; x1 += k2 + 1u;
    TF_R(17) TF_R(29) TF_R(16) TF_R(24)
    x0 += k2; x1 += k0 + 2u;
    TF_R(13) TF_R(15) TF_R(26) TF_R(6)
    x0 += k0; x1 += k1 + 3u;
    TF_R(17) TF_R(29) TF_R(16) TF_R(24)
    x0 += k1; x1 += k2 + 4u;
    TF_R(13) TF_R(15) TF_R(26) TF_R(6)
    x0 += k2; x1 += k0 + 5u;
#undef TF_R
}

// ---------------------------------------------------------------------------
// XLA ErfInv32 (MUFU log) + JAX bits->normal
// ---------------------------------------------------------------------------
__device__ __forceinline__ float erfinv_fast(float x) {
    float w = -__logf(1.0f - x * x);
    float p;
    if (w < 5.0f) {
        w = w - 2.5f;
        p = 2.81022636e-08f;
        p = fmaf(p, w, 3.43273939e-07f);
        p = fmaf(p, w, -3.5233877e-06f);
        p = fmaf(p, w, -4.39150654e-06f);
        p = fmaf(p, w, 0.00021858087f);
        p = fmaf(p, w, -0.00125372503f);
        p = fmaf(p, w, -0.00417768164f);
        p = fmaf(p, w, 0.246640727f);
        p = fmaf(p, w, 1.50140941f);
    } else {
        w = sqrtf(w) - 3.0f;
        p = -0.000200214257f;
        p = fmaf(p, w, 0.000100950558f);
        p = fmaf(p, w, 0.00134934322f);
        p = fmaf(p, w, -0.00367342844f);
        p = fmaf(p, w, 0.00573950773f);
        p = fmaf(p, w, -0.0076224613f);
        p = fmaf(p, w, 0.00943887047f);
        p = fmaf(p, w, 1.00167406f);
        p = fmaf(p, w, 2.83297682f);
    }
    return p * x;
}

__device__ __forceinline__ float bits_to_normal(uint32_t bits) {
    float f = __uint_as_float((bits >> 9) | 0x3f800000u) - 1.0f;
    const float lo = -0.99999994f;
    float u = fmaxf(lo, fmaf(f, 2.0f, lo));
    return 1.41421356f * erfinv_fast(u);
}

// ---------------------------------------------------------------------------
// Kernel: noise scale reduction
// ---------------------------------------------------------------------------
__global__ void reduce_noise_scale(const float* __restrict__ s) {
    __shared__ float ws[32];
    int t = threadIdx.x;
    float4 a = *(const float4*)(s + t * 4);
    float4 b = *(const float4*)(s + 4096 + t * 4);
    float4 c = *(const float4*)(s + 8192 + t * 4);
    float4 d = *(const float4*)(s + 12288 + t * 4);
    float v[16] = {a.x,a.y,a.z,a.w, b.x,b.y,b.z,b.w, c.x,c.y,c.z,c.w, d.x,d.y,d.z,d.w};
    float sum = 0.0f;
#pragma unroll
    for (int i = 0; i < 16; i++) sum += 1.0f / (1.0f + expf(-v[i]));
#pragma unroll
    for (int o = 16; o; o >>= 1) sum += __shfl_xor_sync(0xffffffffu, sum, o);
    if ((t & 31) == 0) ws[t >> 5] = sum;
    __syncthreads();
    if (t < 32) {
        float x = ws[t];
#pragma unroll
        for (int o = 16; o; o >>= 1) x += __shfl_xor_sync(0xffffffffu, x, o);
        if (t == 0) {
            float mean_sig = x / (float)TOKENS;
            g_noise_scale = sqrtf(2.0f * 0.1f * (1.0f + mean_sig * 5.0f));
        }
    }
}

// ---------------------------------------------------------------------------
// Kernel: split A (fp32 -> bf16 hi/lo)
// ---------------------------------------------------------------------------
__device__ __forceinline__ uint32_t pk_bf16(__nv_bfloat16 a, __nv_bfloat16 b) {
    __nv_bfloat162 t(a, b);
    return *reinterpret_cast<uint32_t*>(&t);
}

__global__ __launch_bounds__(256) void split_A(const float* __restrict__ A) {
    size_t i = ((size_t)blockIdx.x * 256 + threadIdx.x) * 4;
    float4 v = *(const float4*)(A + i);
    __nv_bfloat16 h0 = __float2bfloat16(v.x), h1 = __float2bfloat16(v.y);
    __nv_bfloat16 h2 = __float2bfloat16(v.z), h3 = __float2bfloat16(v.w);
    __nv_bfloat16 l0 = __float2bfloat16(v.x - __bfloat162float(h0));
    __nv_bfloat16 l1 = __float2bfloat16(v.y - __bfloat162float(h1));
    __nv_bfloat16 l2 = __float2bfloat16(v.z - __bfloat162float(h2));
    __nv_bfloat16 l3 = __float2bfloat16(v.w - __bfloat162float(h3));
    uint2 uh = { pk_bf16(h0, h1), pk_bf16(h2, h3) };
    uint2 ul = { pk_bf16(l0, l1), pk_bf16(l2, l3) };
    *(uint2*)(g_Ahi + i) = uh;
    *(uint2*)(g_Alo + i) = ul;
}

// ---------------------------------------------------------------------------
// Kernel: split + transpose W  ([K,N] fp32 -> [N,K] bf16 hi/lo)
// ---------------------------------------------------------------------------
__global__ __launch_bounds__(256) void split_W(const float* __restrict__ W) {
    __shared__ float t[64][33];
    int n0 = blockIdx.x * 32, k0 = blockIdx.y * 64;
    int tid = threadIdx.x;
#pragma unroll
    for (int j = 0; j < 8; j++) {
        int idx = tid + j * 256;
        int kr = idx >> 5, nc = idx & 31;
        t[kr][nc] = W[(size_t)(k0 + kr) * DSTATE + n0 + nc];
    }
    __syncthreads();
    int n = tid >> 3, kg = tid & 7;
    uint32_t hi[4], lo[4];
#pragma unroll
    for (int e = 0; e < 8; e += 2) {
        float a = t[kg * 8 + e][n], b = t[kg * 8 + e + 1][n];
        __nv_bfloat16 ha = __float2bfloat16(a), hb = __float2bfloat16(b);
        __nv_bfloat16 la = __float2bfloat16(a - __bfloat162float(ha));
        __nv_bfloat16 lb = __float2bfloat16(b - __bfloat162float(hb));
        hi[e >> 1] = pk_bf16(ha, hb);
        lo[e >> 1] = pk_bf16(la, lb);
    }
    size_t off = (size_t)(n0 + n) * DINNER + k0 + kg * 8;
    *(uint4*)(g_Whi + off) = make_uint4(hi[0], hi[1], hi[2], hi[3]);
    *(uint4*)(g_Wlo + off) = make_uint4(lo[0], lo[1], lo[2], lo[3]);
}

// ---------------------------------------------------------------------------
// Kernel: bf16x3 GEMM via mma.sync (HMMA) + tanh epilogue -> g_pred
// R6-proven best shape: 256 threads, 8 warps 2(M)x4(N), warp tile 64x32,
// CTA tile 128x128x64, 3-stage cp.async, SW128 smem, ldmatrix everything.
// (Measured 260.7us, tensor 64.5%.)
// ---------------------------------------------------------------------------
#define BK 64
#define STAGE_BYTES (64 * 1024)          // Ahi 16K | Alo 16K | Bhi 16K | Blo 16K
#define GEMM_SMEM   (3 * STAGE_BYTES)
#define NCHUNKS     (DINNER / BK)        // 32
#define OFF_ALO 16384
#define OFF_BHI 32768
#define OFF_BLO 49152

__global__ __launch_bounds__(256, 1) void gemm_bf16x3() {
    extern __shared__ char smem[];
    uint32_t sb = smem_u32(smem);
    const int tid = threadIdx.x;
    const int wid = tid >> 5, lid = tid & 31;
    const int bm = blockIdx.y << 7;
    const int bn = blockIdx.x << 7;

    const int wm = (wid & 1) * 64;
    const int wn = (wid >> 1) * 32;

    int goffA[4], goffB[4]; uint32_t soff[4];
#pragma unroll
    for (int i = 0; i < 4; i++) {
        int u = tid + i * 256;
        int r = u >> 3, cu = u & 7;
        goffA[i] = (bm + r) * DINNER + cu * 8;
        goffB[i] = (bn + r) * DINNER + cu * 8;
        soff[i]  = sw128((uint32_t)(r * 128 + cu * 16));
    }

    auto load_chunk = [&](int c, int s) {
        uint32_t st = sb + s * STAGE_BYTES;
        int k0 = c * BK;
#pragma unroll
        for (int i = 0; i < 4; i++) {
            cpa16(st +           soff[i], g_Ahi + goffA[i] + k0);
            cpa16(st + OFF_ALO + soff[i], g_Alo + goffA[i] + k0);
            cpa16(st + OFF_BHI + soff[i], g_Whi + goffB[i] + k0);
            cpa16(st + OFF_BLO + soff[i], g_Wlo + goffB[i] + k0);
        }
        asm volatile("cp.async.commit_group;" ::: "memory");
    };

    float acc[4][4][4];
#pragma unroll
    for (int m = 0; m < 4; m++)
#pragma unroll
        for (int n = 0; n < 4; n++)
#pragma unroll
            for (int j = 0; j < 4; j++) acc[m][n][j] = 0.0f;

    load_chunk(0, 0);
    load_chunk(1, 1);

    const uint32_t a_rb = (uint32_t)(wm + (lid & 15)) * 128;
    const uint32_t a_xm = (uint32_t)((lid & 7) << 4);
    const uint32_t a_kb = (uint32_t)((lid >> 4) * 16);

    const uint32_t b_m  = (uint32_t)(lid >> 3);
    const uint32_t b_r  = (uint32_t)(lid & 7);
    const uint32_t b_xm = b_r << 4;
    const uint32_t b_kb = (b_m & 1) * 16;
    uint32_t b_rb[2];
#pragma unroll
    for (int j = 0; j < 2; j++)
        b_rb[j] = (uint32_t)(wn + (2 * j + (int)(b_m >> 1)) * 8 + (int)b_r) * 128;

    for (int c = 0; c < NCHUNKS; c++) {
        int s = c % 3;
        if (c + 2 < NCHUNKS) load_chunk(c + 2, (c + 2) % 3);

        if (c + 2 < NCHUNKS)      asm volatile("cp.async.wait_group 2;" ::: "memory");
        else if (c + 1 < NCHUNKS) asm volatile("cp.async.wait_group 1;" ::: "memory");
        else                      asm volatile("cp.async.wait_group 0;" ::: "memory");
        __syncthreads();

        uint32_t st = sb + s * STAGE_BYTES;
#pragma unroll
        for (int kk = 0; kk < 4; kk++) {
            uint32_t ah[4][4], al[4][4];
#pragma unroll
            for (int t = 0; t < 4; t++) {
                uint32_t off = a_rb + (uint32_t)(t * 16 * 128)
                             + (((uint32_t)(kk * 32) + a_kb) ^ a_xm);
                ldm_x4(ah[t], st + off);
                ldm_x4(al[t], st + OFF_ALO + off);
            }
            uint32_t bh[4][2], bl[4][2];
#pragma unroll
            for (int j = 0; j < 2; j++) {
                uint32_t off = b_rb[j] + (((uint32_t)(kk * 32) + b_kb) ^ b_xm);
                uint32_t dh[4], dl[4];
                ldm_x4(dh, st + OFF_BHI + off);
                ldm_x4(dl, st + OFF_BLO + off);
                bh[2*j][0] = dh[0]; bh[2*j][1] = dh[1];
                bh[2*j+1][0] = dh[2]; bh[2*j+1][1] = dh[3];
                bl[2*j][0] = dl[0]; bl[2*j][1] = dl[1];
                bl[2*j+1][0] = dl[2]; bl[2*j+1][1] = dl[3];
            }
#pragma unroll
            for (int m = 0; m < 4; m++)
#pragma unroll
                for (int n = 0; n < 4; n++) {
                    mma_bf16(acc[m][n], ah[m], bh[n]);
                    mma_bf16(acc[m][n], ah[m], bl[n]);
                    mma_bf16(acc[m][n], al[m], bh[n]);
                }
        }
        __syncthreads();
    }

    const int r0 = bm + wm + (lid >> 2);
    const int c0 = bn + wn + (lid & 3) * 2;
#pragma unroll
    for (int m = 0; m < 4; m++) {
#pragma unroll
        for (int n = 0; n < 4; n++) {
            float2 lo2 = { fast_tanh(acc[m][n][0]), fast_tanh(acc[m][n][1]) };
            float2 hi2 = { fast_tanh(acc[m][n][2]), fast_tanh(acc[m][n][3]) };
            int row = r0 + m * 16;
            int col = c0 + n * 8;
            *(float2*)(g_pred + (size_t)row * DSTATE + col)       = lo2;
            *(float2*)(g_pred + (size_t)(row + 8) * DSTATE + col) = hi2;
        }
    }
}

// ---------------------------------------------------------------------------
// Kernel: fused 5-step Langevin update, inline JAX threefry noise (MUFU path)
// R7-proven: no g_noise materialization, zero extra DRAM traffic.
// ---------------------------------------------------------------------------
struct FoldedKeys { uint32_t k[10]; };

__global__ __launch_bounds__(256) void step_kernel(const float* __restrict__ h_init,
                                                   float* __restrict__ out,
                                                   FoldedKeys keys) {
    int t = blockIdx.x * blockDim.x + threadIdx.x;
    int base = t * 4;

    float4 h4 = *(const float4*)(h_init + base);
    float4 p4 = *(const float4*)(g_pred + base);
    const float scale = g_noise_scale;

    float hv[4] = {h4.x, h4.y, h4.z, h4.w};
    float pv[4] = {p4.x, p4.y, p4.z, p4.w};

#pragma unroll
    for (int s = 0; s < 5; s++) {
        uint32_t k0 = keys.k[2 * s];
        uint32_t k1 = keys.k[2 * s + 1];
#pragma unroll
        for (int c = 0; c < 4; c++) {
            uint32_t x0 = 0u, x1 = (uint32_t)(base + c);
            threefry2x32(k0, k1, x0, x1);
            float n = bits_to_normal(x0 ^ x1);
            float hh = hv[c];
            hv[c] = fast_tanh(hh - (hh - pv[c]) * 0.1f + n * scale);
        }
    }

    float4 o4 = {hv[0], hv[1], hv[2], hv[3]};
    *(float4*)(out + base) = o4;
}

// ---------------------------------------------------------------------------
// Launch (serial default stream — overlap attempts measured neutral)
// ---------------------------------------------------------------------------
extern "C" void kernel_launch(void* const* d_in, const int* in_sizes, int n_in,
                              void* d_out, int out_size) {
    const float* h_init   = (const float*)d_in[0];
    const float* x_ctx    = (const float*)d_in[1];
    const float* surprise = (const float*)d_in[2];
    const float* weight   = (const float*)d_in[3];
    float* out = (float*)d_out;

    FoldedKeys keys;
    for (int i = 0; i < 5; i++) {
        uint32_t x0 = 0u, x1 = (uint32_t)i;
        threefry2x32(0u, 42u, x0, x1);
        keys.k[2 * i]     = x0;
        keys.k[2 * i + 1] = x1;
    }

    reduce_noise_scale<<<1, 1024>>>(surprise);
    split_A<<<(TOKENS * DINNER) / 1024, 256>>>(x_ctx);
    split_W<<<dim3(DSTATE / 32, DINNER / 64), 256>>>(weight);

    cudaFuncSetAttribute(gemm_bf16x3, cudaFuncAttributeMaxDynamicSharedMemorySize, GEMM_SMEM);
    gemm_bf16x3<<<dim3(DSTATE / 128, TOKENS / 128), 256, GEMM_SMEM>>>();

    step_kernel<<<TOTAL / (256 * 4), 256>>>(h_init, out, keys);
}

// round 13
// speedup vs baseline: 1.1897x; 1.1366x over previous
#include <cuda_runtime.h>
#include <cuda_bf16.h>
#include <cstdint>

#define TOKENS  16384
#define DINNER  2048
#define DSTATE  512
#define TOTAL   (TOKENS * DSTATE)
#define MHALF   (TOKENS / 2)

// ---------------------------------------------------------------------------
// Device-global scratch (no allocation allowed in kernel_launch)
// ---------------------------------------------------------------------------
__device__ float g_noise_scale;
__device__ float g_pred[TOTAL];                         // tanh(X @ W)
__device__ __nv_bfloat16 g_Ahi[TOKENS * DINNER];        // A split hi   [m][k]
__device__ __nv_bfloat16 g_Alo[TOKENS * DINNER];        // A split lo   [m][k]
__device__ __nv_bfloat16 g_Whi[DSTATE * DINNER];        // W^T split hi [n][k]
__device__ __nv_bfloat16 g_Wlo[DSTATE * DINNER];        // W^T split lo [n][k]

// ---------------------------------------------------------------------------
// Helpers
// ---------------------------------------------------------------------------
__device__ __forceinline__ uint32_t smem_u32(const void* p) {
    uint32_t a;
    asm("{ .reg .u64 t; cvta.to.shared.u64 t, %1; cvt.u32.u64 %0, t; }" : "=r"(a) : "l"(p));
    return a;
}

__device__ __forceinline__ uint32_t sw128(uint32_t o) { return o ^ ((o >> 3) & 0x70); }

__device__ __forceinline__ void cpa16(uint32_t s, const void* g) {
    asm volatile("cp.async.cg.shared.global [%0], [%1], 16;" :: "r"(s), "l"(g));
}

__device__ __forceinline__ void ldm_x4(uint32_t* d, uint32_t addr) {
    asm volatile("ldmatrix.sync.aligned.m8n8.x4.shared.b16 {%0,%1,%2,%3}, [%4];"
                 : "=r"(d[0]), "=r"(d[1]), "=r"(d[2]), "=r"(d[3]) : "r"(addr));
}

__device__ __forceinline__ void mma_bf16(float* c, const uint32_t* a, const uint32_t* b) {
    asm volatile("mma.sync.aligned.m16n8k16.row.col.f32.bf16.bf16.f32 "
                 "{%0,%1,%2,%3}, {%4,%5,%6,%7}, {%8,%9}, {%0,%1,%2,%3};"
                 : "+f"(c[0]), "+f"(c[1]), "+f"(c[2]), "+f"(c[3])
                 : "r"(a[0]), "r"(a[1]), "r"(a[2]), "r"(a[3]), "r"(b[0]), "r"(b[1]));
}

// Fast tanh via MUFU exp: abs err ~1e-7.
__device__ __forceinline__ float fast_tanh(float x) {
    float e = __expf(2.0f * x);
    return 1.0f - __fdividef(2.0f, e + 1.0f);
}

// ---------------------------------------------------------------------------
// Threefry-2x32 (JAX-compatible, 20 rounds)
// ---------------------------------------------------------------------------
__host__ __device__ __forceinline__ uint32_t rotl32(uint32_t x, int r) {
    return (x << r) | (x >> (32 - r));
}

__host__ __device__ __forceinline__ void threefry2x32(uint32_t k0, uint32_t k1,
                                                      uint32_t& x0, uint32_t& x1) {
    uint32_t k2 = k0 ^ k1 ^ 0x1BD11BDAu;
    x0 += k0; x1 += k1;
#define TF_R(r) { x0 += x1; x1 = rotl32(x1, (r)); x1 ^= x0; }
    TF_R(13) TF_R(15) TF_R(26) TF_R(6)
    x0 += k1; x1 += k2 + 1u;
    TF_R(17) TF_R(29) TF_R(16) TF_R(24)
    x0 += k2; x1 += k0 + 2u;
    TF_R(13) TF_R(15) TF_R(26) TF_R(6)
    x0 += k0; x1 += k1 + 3u;
    TF_R(17) TF_R(29) TF_R(16) TF_R(24)
    x0 += k1; x1 += k2 + 4u;
    TF_R(13) TF_R(15) TF_R(26) TF_R(6)
    x0 += k2; x1 += k0 + 5u;
#undef TF_R
}

// ---------------------------------------------------------------------------
// XLA ErfInv32 (MUFU log) + JAX bits->normal
// ---------------------------------------------------------------------------
__device__ __forceinline__ float erfinv_fast(float x) {
    float w = -__logf(1.0f - x * x);
    float p;
    if (w < 5.0f) {
        w = w - 2.5f;
        p = 2.81022636e-08f;
        p = fmaf(p, w, 3.43273939e-07f);
        p = fmaf(p, w, -3.5233877e-06f);
        p = fmaf(p, w, -4.39150654e-06f);
        p = fmaf(p, w, 0.00021858087f);
        p = fmaf(p, w, -0.00125372503f);
        p = fmaf(p, w, -0.00417768164f);
        p = fmaf(p, w, 0.246640727f);
        p = fmaf(p, w, 1.50140941f);
    } else {
        w = sqrtf(w) - 3.0f;
        p = -0.000200214257f;
        p = fmaf(p, w, 0.000100950558f);
        p = fmaf(p, w, 0.00134934322f);
        p = fmaf(p, w, -0.00367342844f);
        p = fmaf(p, w, 0.00573950773f);
        p = fmaf(p, w, -0.0076224613f);
        p = fmaf(p, w, 0.00943887047f);
        p = fmaf(p, w, 1.00167406f);
        p = fmaf(p, w, 2.83297682f);
    }
    return p * x;
}

__device__ __forceinline__ float bits_to_normal(uint32_t bits) {
    float f = __uint_as_float((bits >> 9) | 0x3f800000u) - 1.0f;
    const float lo = -0.99999994f;
    float u = fmaxf(lo, fmaf(f, 2.0f, lo));
    return 1.41421356f * erfinv_fast(u);
}

// ---------------------------------------------------------------------------
// Kernel: noise scale reduction
// ---------------------------------------------------------------------------
__global__ void reduce_noise_scale(const float* __restrict__ s) {
    __shared__ float ws[32];
    int t = threadIdx.x;
    float4 a = *(const float4*)(s + t * 4);
    float4 b = *(const float4*)(s + 4096 + t * 4);
    float4 c = *(const float4*)(s + 8192 + t * 4);
    float4 d = *(const float4*)(s + 12288 + t * 4);
    float v[16] = {a.x,a.y,a.z,a.w, b.x,b.y,b.z,b.w, c.x,c.y,c.z,c.w, d.x,d.y,d.z,d.w};
    float sum = 0.0f;
#pragma unroll
    for (int i = 0; i < 16; i++) sum += 1.0f / (1.0f + expf(-v[i]));
#pragma unroll
    for (int o = 16; o; o >>= 1) sum += __shfl_xor_sync(0xffffffffu, sum, o);
    if ((t & 31) == 0) ws[t >> 5] = sum;
    __syncthreads();
    if (t < 32) {
        float x = ws[t];
#pragma unroll
        for (int o = 16; o; o >>= 1) x += __shfl_xor_sync(0xffffffffu, x, o);
        if (t == 0) {
            float mean_sig = x / (float)TOKENS;
            g_noise_scale = sqrtf(2.0f * 0.1f * (1.0f + mean_sig * 5.0f));
        }
    }
}

// ---------------------------------------------------------------------------
// Kernel: split A (fp32 -> bf16 hi/lo); elem_base selects the M-half
// ---------------------------------------------------------------------------
__device__ __forceinline__ uint32_t pk_bf16(__nv_bfloat16 a, __nv_bfloat16 b) {
    __nv_bfloat162 t(a, b);
    return *reinterpret_cast<uint32_t*>(&t);
}

__global__ __launch_bounds__(256) void split_A(const float* __restrict__ A,
                                               size_t elem_base) {
    size_t i = elem_base + ((size_t)blockIdx.x * 256 + threadIdx.x) * 4;
    float4 v = *(const float4*)(A + i);
    __nv_bfloat16 h0 = __float2bfloat16(v.x), h1 = __float2bfloat16(v.y);
    __nv_bfloat16 h2 = __float2bfloat16(v.z), h3 = __float2bfloat16(v.w);
    __nv_bfloat16 l0 = __float2bfloat16(v.x - __bfloat162float(h0));
    __nv_bfloat16 l1 = __float2bfloat16(v.y - __bfloat162float(h1));
    __nv_bfloat16 l2 = __float2bfloat16(v.z - __bfloat162float(h2));
    __nv_bfloat16 l3 = __float2bfloat16(v.w - __bfloat162float(h3));
    uint2 uh = { pk_bf16(h0, h1), pk_bf16(h2, h3) };
    uint2 ul = { pk_bf16(l0, l1), pk_bf16(l2, l3) };
    *(uint2*)(g_Ahi + i) = uh;
    *(uint2*)(g_Alo + i) = ul;
}

// ---------------------------------------------------------------------------
// Kernel: split + transpose W  ([K,N] fp32 -> [N,K] bf16 hi/lo)
// ---------------------------------------------------------------------------
__global__ __launch_bounds__(256) void split_W(const float* __restrict__ W) {
    __shared__ float t[64][33];
    int n0 = blockIdx.x * 32, k0 = blockIdx.y * 64;
    int tid = threadIdx.x;
#pragma unroll
    for (int j = 0; j < 8; j++) {
        int idx = tid + j * 256;
        int kr = idx >> 5, nc = idx & 31;
        t[kr][nc] = W[(size_t)(k0 + kr) * DSTATE + n0 + nc];
    }
    __syncthreads();
    int n = tid >> 3, kg = tid & 7;
    uint32_t hi[4], lo[4];
#pragma unroll
    for (int e = 0; e < 8; e += 2) {
        float a = t[kg * 8 + e][n], b = t[kg * 8 + e + 1][n];
        __nv_bfloat16 ha = __float2bfloat16(a), hb = __float2bfloat16(b);
        __nv_bfloat16 la = __float2bfloat16(a - __bfloat162float(ha));
        __nv_bfloat16 lb = __float2bfloat16(b - __bfloat162float(hb));
        hi[e >> 1] = pk_bf16(ha, hb);
        lo[e >> 1] = pk_bf16(la, lb);
    }
    size_t off = (size_t)(n0 + n) * DINNER + k0 + kg * 8;
    *(uint4*)(g_Whi + off) = make_uint4(hi[0], hi[1], hi[2], hi[3]);
    *(uint4*)(g_Wlo + off) = make_uint4(lo[0], lo[1], lo[2], lo[3]);
}

// ---------------------------------------------------------------------------
// Kernel: bf16x3 GEMM (R6-proven shape) + tanh epilogue -> g_pred
// m_base selects the M-half handled by this launch.
// ---------------------------------------------------------------------------
#define BK 64
#define STAGE_BYTES (64 * 1024)
#define GEMM_SMEM   (3 * STAGE_BYTES)
#define NCHUNKS     (DINNER / BK)
#define OFF_ALO 16384
#define OFF_BHI 32768
#define OFF_BLO 49152

__global__ __launch_bounds__(256, 1) void gemm_bf16x3(int m_base) {
    extern __shared__ char smem[];
    uint32_t sb = smem_u32(smem);
    const int tid = threadIdx.x;
    const int wid = tid >> 5, lid = tid & 31;
    const int bm = m_base + (blockIdx.y << 7);
    const int bn = blockIdx.x << 7;

    const int wm = (wid & 1) * 64;
    const int wn = (wid >> 1) * 32;

    int goffA[4], goffB[4]; uint32_t soff[4];
#pragma unroll
    for (int i = 0; i < 4; i++) {
        int u = tid + i * 256;
        int r = u >> 3, cu = u & 7;
        goffA[i] = (bm + r) * DINNER + cu * 8;
        goffB[i] = (bn + r) * DINNER + cu * 8;
        soff[i]  = sw128((uint32_t)(r * 128 + cu * 16));
    }

    auto load_chunk = [&](int c, int s) {
        uint32_t st = sb + s * STAGE_BYTES;
        int k0 = c * BK;
#pragma unroll
        for (int i = 0; i < 4; i++) {
            cpa16(st +           soff[i], g_Ahi + goffA[i] + k0);
            cpa16(st + OFF_ALO + soff[i], g_Alo + goffA[i] + k0);
            cpa16(st + OFF_BHI + soff[i], g_Whi + goffB[i] + k0);
            cpa16(st + OFF_BLO + soff[i], g_Wlo + goffB[i] + k0);
        }
        asm volatile("cp.async.commit_group;" ::: "memory");
    };

    float acc[4][4][4];
#pragma unroll
    for (int m = 0; m < 4; m++)
#pragma unroll
        for (int n = 0; n < 4; n++)
#pragma unroll
            for (int j = 0; j < 4; j++) acc[m][n][j] = 0.0f;

    load_chunk(0, 0);
    load_chunk(1, 1);

    const uint32_t a_rb = (uint32_t)(wm + (lid & 15)) * 128;
    const uint32_t a_xm = (uint32_t)((lid & 7) << 4);
    const uint32_t a_kb = (uint32_t)((lid >> 4) * 16);

    const uint32_t b_m  = (uint32_t)(lid >> 3);
    const uint32_t b_r  = (uint32_t)(lid & 7);
    const uint32_t b_xm = b_r << 4;
    const uint32_t b_kb = (b_m & 1) * 16;
    uint32_t b_rb[2];
#pragma unroll
    for (int j = 0; j < 2; j++)
        b_rb[j] = (uint32_t)(wn + (2 * j + (int)(b_m >> 1)) * 8 + (int)b_r) * 128;

    for (int c = 0; c < NCHUNKS; c++) {
        int s = c % 3;
        if (c + 2 < NCHUNKS) load_chunk(c + 2, (c + 2) % 3);

        if (c + 2 < NCHUNKS)      asm volatile("cp.async.wait_group 2;" ::: "memory");
        else if (c + 1 < NCHUNKS) asm volatile("cp.async.wait_group 1;" ::: "memory");
        else                      asm volatile("cp.async.wait_group 0;" ::: "memory");
        __syncthreads();

        uint32_t st = sb + s * STAGE_BYTES;
#pragma unroll
        for (int kk = 0; kk < 4; kk++) {
            uint32_t ah[4][4], al[4][4];
#pragma unroll
            for (int t = 0; t < 4; t++) {
                uint32_t off = a_rb + (uint32_t)(t * 16 * 128)
                             + (((uint32_t)(kk * 32) + a_kb) ^ a_xm);
                ldm_x4(ah[t], st + off);
                ldm_x4(al[t], st + OFF_ALO + off);
            }
            uint32_t bh[4][2], bl[4][2];
#pragma unroll
            for (int j = 0; j < 2; j++) {
                uint32_t off = b_rb[j] + (((uint32_t)(kk * 32) + b_kb) ^ b_xm);
                uint32_t dh[4], dl[4];
                ldm_x4(dh, st + OFF_BHI + off);
                ldm_x4(dl, st + OFF_BLO + off);
                bh[2*j][0] = dh[0]; bh[2*j][1] = dh[1];
                bh[2*j+1][0] = dh[2]; bh[2*j+1][1] = dh[3];
                bl[2*j][0] = dl[0]; bl[2*j][1] = dl[1];
                bl[2*j+1][0] = dl[2]; bl[2*j+1][1] = dl[3];
            }
#pragma unroll
            for (int m = 0; m < 4; m++)
#pragma unroll
                for (int n = 0; n < 4; n++) {
                    mma_bf16(acc[m][n], ah[m], bh[n]);
                    mma_bf16(acc[m][n], ah[m], bl[n]);
                    mma_bf16(acc[m][n], al[m], bh[n]);
                }
        }
        __syncthreads();
    }

    const int r0 = bm + wm + (lid >> 2);
    const int c0 = bn + wn + (lid & 3) * 2;
#pragma unroll
    for (int m = 0; m < 4; m++) {
#pragma unroll
        for (int n = 0; n < 4; n++) {
            float2 lo2 = { fast_tanh(acc[m][n][0]), fast_tanh(acc[m][n][1]) };
            float2 hi2 = { fast_tanh(acc[m][n][2]), fast_tanh(acc[m][n][3]) };
            int row = r0 + m * 16;
            int col = c0 + n * 8;
            *(float2*)(g_pred + (size_t)row * DSTATE + col)       = lo2;
            *(float2*)(g_pred + (size_t)(row + 8) * DSTATE + col) = hi2;
        }
    }
}

// ---------------------------------------------------------------------------
// Kernel: fused 5-step Langevin update, inline JAX threefry noise (MUFU path)
// elem_base selects the M-half.
// ---------------------------------------------------------------------------
struct FoldedKeys { uint32_t k[10]; };

__global__ __launch_bounds__(256) void step_kernel(const float* __restrict__ h_init,
                                                   float* __restrict__ out,
                                                   FoldedKeys keys, int elem_base) {
    int t = blockIdx.x * blockDim.x + threadIdx.x;
    int base = elem_base + t * 4;

    float4 h4 = *(const float4*)(h_init + base);
    float4 p4 = *(const float4*)(g_pred + base);
    const float scale = g_noise_scale;

    float hv[4] = {h4.x, h4.y, h4.z, h4.w};
    float pv[4] = {p4.x, p4.y, p4.z, p4.w};

#pragma unroll
    for (int s = 0; s < 5; s++) {
        uint32_t k0 = keys.k[2 * s];
        uint32_t k1 = keys.k[2 * s + 1];
#pragma unroll
        for (int c = 0; c < 4; c++) {
            uint32_t x0 = 0u, x1 = (uint32_t)(base + c);
            threefry2x32(k0, k1, x0, x1);
            float n = bits_to_normal(x0 ^ x1);
            float hh = hv[c];
            hv[c] = fast_tanh(hh - (hh - pv[c]) * 0.1f + n * scale);
        }
    }

    float4 o4 = {hv[0], hv[1], hv[2], hv[3]};
    *(float4*)(out + base) = o4;
}

// ---------------------------------------------------------------------------
// Launch: 2-way M-pipelined schedule.
//   stream0: reduce, split_W, splitA_h0, splitA_h1, step_h0, step_h1
//   s1: GEMM_h0 (after splitA_h0);  s2: GEMM_h1 (after splitA_h1)
// splitA_h1 overlaps GEMM_h0; GEMM_h1 fills GEMM_h0's retiring wave;
// step_h0 overlaps GEMM_h1's tail.
// ---------------------------------------------------------------------------
extern "C" void kernel_launch(void* const* d_in, const int* in_sizes, int n_in,
                              void* d_out, int out_size) {
    const float* h_init   = (const float*)d_in[0];
    const float* x_ctx    = (const float*)d_in[1];
    const float* surprise = (const float*)d_in[2];
    const float* weight   = (const float*)d_in[3];
    float* out = (float*)d_out;

    FoldedKeys keys;
    for (int i = 0; i < 5; i++) {
        uint32_t x0 = 0u, x1 = (uint32_t)i;
        threefry2x32(0u, 42u, x0, x1);
        keys.k[2 * i]     = x0;
        keys.k[2 * i + 1] = x1;
    }

    static cudaStream_t s1 = nullptr, s2 = nullptr;
    static cudaEvent_t eA0 = nullptr, eA1 = nullptr, ePre = nullptr,
                       eG0 = nullptr, eG1 = nullptr;
    if (!s1) {
        cudaStreamCreateWithFlags(&s1, cudaStreamNonBlocking);
        cudaStreamCreateWithFlags(&s2, cudaStreamNonBlocking);
        cudaEventCreateWithFlags(&eA0, cudaEventDisableTiming);
        cudaEventCreateWithFlags(&eA1, cudaEventDisableTiming);
        cudaEventCreateWithFlags(&ePre, cudaEventDisableTiming);
        cudaEventCreateWithFlags(&eG0, cudaEventDisableTiming);
        cudaEventCreateWithFlags(&eG1, cudaEventDisableTiming);
    }

    cudaFuncSetAttribute(gemm_bf16x3, cudaFuncAttributeMaxDynamicSharedMemorySize, GEMM_SMEM);

    const size_t HALF_ELEMS = (size_t)MHALF * DINNER;   // A elements per half
    const int    SPLITA_BLKS = (int)(HALF_ELEMS / 1024);
    const dim3   GEMM_GRID(DSTATE / 128, MHALF / 128);
    const int    STEP_BLKS = (TOTAL / 2) / (256 * 4);

    // stream0: tiny prologue
    reduce_noise_scale<<<1, 1024>>>(surprise);
    split_W<<<dim3(DSTATE / 32, DINNER / 64), 256>>>(weight);
    cudaEventRecord(ePre, 0);

    // stream0: split A half 0
    split_A<<<SPLITA_BLKS, 256>>>(x_ctx, 0);
    cudaEventRecord(eA0, 0);

    // s1: GEMM half 0 (waits splitA_h0 + prologue)
    cudaStreamWaitEvent(s1, eA0, 0);
    cudaStreamWaitEvent(s1, ePre, 0);
    gemm_bf16x3<<<GEMM_GRID, 256, GEMM_SMEM, s1>>>(0);
    cudaEventRecord(eG0, s1);

    // stream0: split A half 1 (runs concurrent with GEMM_h0)
    split_A<<<SPLITA_BLKS, 256>>>(x_ctx, HALF_ELEMS);
    cudaEventRecord(eA1, 0);

    // s2: GEMM half 1 (waits splitA_h1 + prologue; fills GEMM_h0's tail)
    cudaStreamWaitEvent(s2, eA1, 0);
    cudaStreamWaitEvent(s2, ePre, 0);
    gemm_bf16x3<<<GEMM_GRID, 256, GEMM_SMEM, s2>>>(MHALF);
    cudaEventRecord(eG1, s2);

    // stream0: step halves (h0 overlaps GEMM_h1's remainder)
    cudaStreamWaitEvent(0, eG0, 0);
    step_kernel<<<STEP_BLKS, 256>>>(h_init, out, keys, 0);
    cudaStreamWaitEvent(0, eG1, 0);
    step_kernel<<<STEP_BLKS, 256>>>(h_init, out, keys, TOTAL / 2);
}

// round 14
// speedup vs baseline: 1.2752x; 1.0719x over previous
#include <cuda_runtime.h>
#include <cuda_bf16.h>
#include <cstdint>

#define TOKENS  16384
#define DINNER  2048
#define DSTATE  512
#define TOTAL   (TOKENS * DSTATE)
#define MQUART  (TOKENS / 4)

// ---------------------------------------------------------------------------
// Device-global scratch (no allocation allowed in kernel_launch)
// ---------------------------------------------------------------------------
__device__ float g_noise_scale;
__device__ float g_pred[TOTAL];                         // tanh(X @ W)
__device__ __nv_bfloat16 g_Ahi[TOKENS * DINNER];        // A split hi   [m][k]
__device__ __nv_bfloat16 g_Alo[TOKENS * DINNER];        // A split lo   [m][k]
__device__ __nv_bfloat16 g_Whi[DSTATE * DINNER];        // W^T split hi [n][k]
__device__ __nv_bfloat16 g_Wlo[DSTATE * DINNER];        // W^T split lo [n][k]

// ---------------------------------------------------------------------------
// Helpers
// ---------------------------------------------------------------------------
__device__ __forceinline__ uint32_t smem_u32(const void* p) {
    uint32_t a;
    asm("{ .reg .u64 t; cvta.to.shared.u64 t, %1; cvt.u32.u64 %0, t; }" : "=r"(a) : "l"(p));
    return a;
}

__device__ __forceinline__ uint32_t sw128(uint32_t o) { return o ^ ((o >> 3) & 0x70); }

__device__ __forceinline__ void cpa16(uint32_t s, const void* g) {
    asm volatile("cp.async.cg.shared.global [%0], [%1], 16;" :: "r"(s), "l"(g));
}

__device__ __forceinline__ void ldm_x4(uint32_t* d, uint32_t addr) {
    asm volatile("ldmatrix.sync.aligned.m8n8.x4.shared.b16 {%0,%1,%2,%3}, [%4];"
                 : "=r"(d[0]), "=r"(d[1]), "=r"(d[2]), "=r"(d[3]) : "r"(addr));
}

__device__ __forceinline__ void mma_bf16(float* c, const uint32_t* a, const uint32_t* b) {
    asm volatile("mma.sync.aligned.m16n8k16.row.col.f32.bf16.bf16.f32 "
                 "{%0,%1,%2,%3}, {%4,%5,%6,%7}, {%8,%9}, {%0,%1,%2,%3};"
                 : "+f"(c[0]), "+f"(c[1]), "+f"(c[2]), "+f"(c[3])
                 : "r"(a[0]), "r"(a[1]), "r"(a[2]), "r"(a[3]), "r"(b[0]), "r"(b[1]));
}

// Fast tanh via MUFU exp: abs err ~1e-7.
__device__ __forceinline__ float fast_tanh(float x) {
    float e = __expf(2.0f * x);
    return 1.0f - __fdividef(2.0f, e + 1.0f);
}

// ---------------------------------------------------------------------------
// Threefry-2x32 (JAX-compatible, 20 rounds)
// ---------------------------------------------------------------------------
__host__ __device__ __forceinline__ uint32_t rotl32(uint32_t x, int r) {
    return (x << r) | (x >> (32 - r));
}

__host__ __device__ __forceinline__ void threefry2x32(uint32_t k0, uint32_t k1,
                                                      uint32_t& x0, uint32_t& x1) {
    uint32_t k2 = k0 ^ k1 ^ 0x1BD11BDAu;
    x0 += k0; x1 += k1;
#define TF_R(r) { x0 += x1; x1 = rotl32(x1, (r)); x1 ^= x0; }
    TF_R(13) TF_R(15) TF_R(26) TF_R(6)
    x0 += k1; x1 += k2 + 1u;
    TF_R(17) TF_R(29) TF_R(16) TF_R(24)
    x0 += k2; x1 += k0 + 2u;
    TF_R(13) TF_R(15) TF_R(26) TF_R(6)
    x0 += k0; x1 += k1 + 3u;
    TF_R(17) TF_R(29) TF_R(16) TF_R(24)
    x0 += k1; x1 += k2 + 4u;
    TF_R(13) TF_R(15) TF_R(26) TF_R(6)
    x0 += k2; x1 += k0 + 5u;
#undef TF_R
}

// ---------------------------------------------------------------------------
// XLA ErfInv32 (MUFU log) + JAX bits->normal
// ---------------------------------------------------------------------------
__device__ __forceinline__ float erfinv_fast(float x) {
    float w = -__logf(1.0f - x * x);
    float p;
    if (w < 5.0f) {
        w = w - 2.5f;
        p = 2.81022636e-08f;
        p = fmaf(p, w, 3.43273939e-07f);
        p = fmaf(p, w, -3.5233877e-06f);
        p = fmaf(p, w, -4.39150654e-06f);
        p = fmaf(p, w, 0.00021858087f);
        p = fmaf(p, w, -0.00125372503f);
        p = fmaf(p, w, -0.00417768164f);
        p = fmaf(p, w, 0.246640727f);
        p = fmaf(p, w, 1.50140941f);
    } else {
        w = sqrtf(w) - 3.0f;
        p = -0.000200214257f;
        p = fmaf(p, w, 0.000100950558f);
        p = fmaf(p, w, 0.00134934322f);
        p = fmaf(p, w, -0.00367342844f);
        p = fmaf(p, w, 0.00573950773f);
        p = fmaf(p, w, -0.0076224613f);
        p = fmaf(p, w, 0.00943887047f);
        p = fmaf(p, w, 1.00167406f);
        p = fmaf(p, w, 2.83297682f);
    }
    return p * x;
}

__device__ __forceinline__ float bits_to_normal(uint32_t bits) {
    float f = __uint_as_float((bits >> 9) | 0x3f800000u) - 1.0f;
    const float lo = -0.99999994f;
    float u = fmaxf(lo, fmaf(f, 2.0f, lo));
    return 1.41421356f * erfinv_fast(u);
}

// ---------------------------------------------------------------------------
// Kernel: noise scale reduction
// ---------------------------------------------------------------------------
__global__ void reduce_noise_scale(const float* __restrict__ s) {
    __shared__ float ws[32];
    int t = threadIdx.x;
    float4 a = *(const float4*)(s + t * 4);
    float4 b = *(const float4*)(s + 4096 + t * 4);
    float4 c = *(const float4*)(s + 8192 + t * 4);
    float4 d = *(const float4*)(s + 12288 + t * 4);
    float v[16] = {a.x,a.y,a.z,a.w, b.x,b.y,b.z,b.w, c.x,c.y,c.z,c.w, d.x,d.y,d.z,d.w};
    float sum = 0.0f;
#pragma unroll
    for (int i = 0; i < 16; i++) sum += 1.0f / (1.0f + expf(-v[i]));
#pragma unroll
    for (int o = 16; o; o >>= 1) sum += __shfl_xor_sync(0xffffffffu, sum, o);
    if ((t & 31) == 0) ws[t >> 5] = sum;
    __syncthreads();
    if (t < 32) {
        float x = ws[t];
#pragma unroll
        for (int o = 16; o; o >>= 1) x += __shfl_xor_sync(0xffffffffu, x, o);
        if (t == 0) {
            float mean_sig = x / (float)TOKENS;
            g_noise_scale = sqrtf(2.0f * 0.1f * (1.0f + mean_sig * 5.0f));
        }
    }
}

// ---------------------------------------------------------------------------
// Kernel: split A (fp32 -> bf16 hi/lo); elem_base selects the M-chunk
// ---------------------------------------------------------------------------
__device__ __forceinline__ uint32_t pk_bf16(__nv_bfloat16 a, __nv_bfloat16 b) {
    __nv_bfloat162 t(a, b);
    return *reinterpret_cast<uint32_t*>(&t);
}

__global__ __launch_bounds__(256) void split_A(const float* __restrict__ A,
                                               size_t elem_base) {
    size_t i = elem_base + ((size_t)blockIdx.x * 256 + threadIdx.x) * 4;
    float4 v = *(const float4*)(A + i);
    __nv_bfloat16 h0 = __float2bfloat16(v.x), h1 = __float2bfloat16(v.y);
    __nv_bfloat16 h2 = __float2bfloat16(v.z), h3 = __float2bfloat16(v.w);
    __nv_bfloat16 l0 = __float2bfloat16(v.x - __bfloat162float(h0));
    __nv_bfloat16 l1 = __float2bfloat16(v.y - __bfloat162float(h1));
    __nv_bfloat16 l2 = __float2bfloat16(v.z - __bfloat162float(h2));
    __nv_bfloat16 l3 = __float2bfloat16(v.w - __bfloat162float(h3));
    uint2 uh = { pk_bf16(h0, h1), pk_bf16(h2, h3) };
    uint2 ul = { pk_bf16(l0, l1), pk_bf16(l2, l3) };
    *(uint2*)(g_Ahi + i) = uh;
    *(uint2*)(g_Alo + i) = ul;
}

// ---------------------------------------------------------------------------
// Kernel: split + transpose W  ([K,N] fp32 -> [N,K] bf16 hi/lo)
// ---------------------------------------------------------------------------
__global__ __launch_bounds__(256) void split_W(const float* __restrict__ W) {
    __shared__ float t[64][33];
    int n0 = blockIdx.x * 32, k0 = blockIdx.y * 64;
    int tid = threadIdx.x;
#pragma unroll
    for (int j = 0; j < 8; j++) {
        int idx = tid + j * 256;
        int kr = idx >> 5, nc = idx & 31;
        t[kr][nc] = W[(size_t)(k0 + kr) * DSTATE + n0 + nc];
    }
    __syncthreads();
    int n = tid >> 3, kg = tid & 7;
    uint32_t hi[4], lo[4];
#pragma unroll
    for (int e = 0; e < 8; e += 2) {
        float a = t[kg * 8 + e][n], b = t[kg * 8 + e + 1][n];
        __nv_bfloat16 ha = __float2bfloat16(a), hb = __float2bfloat16(b);
        __nv_bfloat16 la = __float2bfloat16(a - __bfloat162float(ha));
        __nv_bfloat16 lb = __float2bfloat16(b - __bfloat162float(hb));
        hi[e >> 1] = pk_bf16(ha, hb);
        lo[e >> 1] = pk_bf16(la, lb);
    }
    size_t off = (size_t)(n0 + n) * DINNER + k0 + kg * 8;
    *(uint4*)(g_Whi + off) = make_uint4(hi[0], hi[1], hi[2], hi[3]);
    *(uint4*)(g_Wlo + off) = make_uint4(lo[0], lo[1], lo[2], lo[3]);
}

// ---------------------------------------------------------------------------
// Kernel: bf16x3 GEMM (R6-proven shape) + tanh epilogue -> g_pred
// m_base selects the M-chunk handled by this launch.
// ---------------------------------------------------------------------------
#define BK 64
#define STAGE_BYTES (64 * 1024)
#define GEMM_SMEM   (3 * STAGE_BYTES)
#define NCHUNKS     (DINNER / BK)
#define OFF_ALO 16384
#define OFF_BHI 32768
#define OFF_BLO 49152

__global__ __launch_bounds__(256, 1) void gemm_bf16x3(int m_base) {
    extern __shared__ char smem[];
    uint32_t sb = smem_u32(smem);
    const int tid = threadIdx.x;
    const int wid = tid >> 5, lid = tid & 31;
    const int bm = m_base + (blockIdx.y << 7);
    const int bn = blockIdx.x << 7;

    const int wm = (wid & 1) * 64;
    const int wn = (wid >> 1) * 32;

    int goffA[4], goffB[4]; uint32_t soff[4];
#pragma unroll
    for (int i = 0; i < 4; i++) {
        int u = tid + i * 256;
        int r = u >> 3, cu = u & 7;
        goffA[i] = (bm + r) * DINNER + cu * 8;
        goffB[i] = (bn + r) * DINNER + cu * 8;
        soff[i]  = sw128((uint32_t)(r * 128 + cu * 16));
    }

    auto load_chunk = [&](int c, int s) {
        uint32_t st = sb + s * STAGE_BYTES;
        int k0 = c * BK;
#pragma unroll
        for (int i = 0; i < 4; i++) {
            cpa16(st +           soff[i], g_Ahi + goffA[i] + k0);
            cpa16(st + OFF_ALO + soff[i], g_Alo + goffA[i] + k0);
            cpa16(st + OFF_BHI + soff[i], g_Whi + goffB[i] + k0);
            cpa16(st + OFF_BLO + soff[i], g_Wlo + goffB[i] + k0);
        }
        asm volatile("cp.async.commit_group;" ::: "memory");
    };

    float acc[4][4][4];
#pragma unroll
    for (int m = 0; m < 4; m++)
#pragma unroll
        for (int n = 0; n < 4; n++)
#pragma unroll
            for (int j = 0; j < 4; j++) acc[m][n][j] = 0.0f;

    load_chunk(0, 0);
    load_chunk(1, 1);

    const uint32_t a_rb = (uint32_t)(wm + (lid & 15)) * 128;
    const uint32_t a_xm = (uint32_t)((lid & 7) << 4);
    const uint32_t a_kb = (uint32_t)((lid >> 4) * 16);

    const uint32_t b_m  = (uint32_t)(lid >> 3);
    const uint32_t b_r  = (uint32_t)(lid & 7);
    const uint32_t b_xm = b_r << 4;
    const uint32_t b_kb = (b_m & 1) * 16;
    uint32_t b_rb[2];
#pragma unroll
    for (int j = 0; j < 2; j++)
        b_rb[j] = (uint32_t)(wn + (2 * j + (int)(b_m >> 1)) * 8 + (int)b_r) * 128;

    for (int c = 0; c < NCHUNKS; c++) {
        int s = c % 3;
        if (c + 2 < NCHUNKS) load_chunk(c + 2, (c + 2) % 3);

        if (c + 2 < NCHUNKS)      asm volatile("cp.async.wait_group 2;" ::: "memory");
        else if (c + 1 < NCHUNKS) asm volatile("cp.async.wait_group 1;" ::: "memory");
        else                      asm volatile("cp.async.wait_group 0;" ::: "memory");
        __syncthreads();

        uint32_t st = sb + s * STAGE_BYTES;
#pragma unroll
        for (int kk = 0; kk < 4; kk++) {
            uint32_t ah[4][4], al[4][4];
#pragma unroll
            for (int t = 0; t < 4; t++) {
                uint32_t off = a_rb + (uint32_t)(t * 16 * 128)
                             + (((uint32_t)(kk * 32) + a_kb) ^ a_xm);
                ldm_x4(ah[t], st + off);
                ldm_x4(al[t], st + OFF_ALO + off);
            }
            uint32_t bh[4][2], bl[4][2];
#pragma unroll
            for (int j = 0; j < 2; j++) {
                uint32_t off = b_rb[j] + (((uint32_t)(kk * 32) + b_kb) ^ b_xm);
                uint32_t dh[4], dl[4];
                ldm_x4(dh, st + OFF_BHI + off);
                ldm_x4(dl, st + OFF_BLO + off);
                bh[2*j][0] = dh[0]; bh[2*j][1] = dh[1];
                bh[2*j+1][0] = dh[2]; bh[2*j+1][1] = dh[3];
                bl[2*j][0] = dl[0]; bl[2*j][1] = dl[1];
                bl[2*j+1][0] = dl[2]; bl[2*j+1][1] = dl[3];
            }
#pragma unroll
            for (int m = 0; m < 4; m++)
#pragma unroll
                for (int n = 0; n < 4; n++) {
                    mma_bf16(acc[m][n], ah[m], bh[n]);
                    mma_bf16(acc[m][n], ah[m], bl[n]);
                    mma_bf16(acc[m][n], al[m], bh[n]);
                }
        }
        __syncthreads();
    }

    const int r0 = bm + wm + (lid >> 2);
    const int c0 = bn + wn + (lid & 3) * 2;
#pragma unroll
    for (int m = 0; m < 4; m++) {
#pragma unroll
        for (int n = 0; n < 4; n++) {
            float2 lo2 = { fast_tanh(acc[m][n][0]), fast_tanh(acc[m][n][1]) };
            float2 hi2 = { fast_tanh(acc[m][n][2]), fast_tanh(acc[m][n][3]) };
            int row = r0 + m * 16;
            int col = c0 + n * 8;
            *(float2*)(g_pred + (size_t)row * DSTATE + col)       = lo2;
            *(float2*)(g_pred + (size_t)(row + 8) * DSTATE + col) = hi2;
        }
    }
}

// ---------------------------------------------------------------------------
// Kernel: fused 5-step Langevin update, inline JAX threefry noise (MUFU path)
// ---------------------------------------------------------------------------
struct FoldedKeys { uint32_t k[10]; };

__global__ __launch_bounds__(256) void step_kernel(const float* __restrict__ h_init,
                                                   float* __restrict__ out,
                                                   FoldedKeys keys, int elem_base) {
    int t = blockIdx.x * blockDim.x + threadIdx.x;
    int base = elem_base + t * 4;

    float4 h4 = *(const float4*)(h_init + base);
    float4 p4 = *(const float4*)(g_pred + base);
    const float scale = g_noise_scale;

    float hv[4] = {h4.x, h4.y, h4.z, h4.w};
    float pv[4] = {p4.x, p4.y, p4.z, p4.w};

#pragma unroll
    for (int s = 0; s < 5; s++) {
        uint32_t k0 = keys.k[2 * s];
        uint32_t k1 = keys.k[2 * s + 1];
#pragma unroll
        for (int c = 0; c < 4; c++) {
            uint32_t x0 = 0u, x1 = (uint32_t)(base + c);
            threefry2x32(k0, k1, x0, x1);
            float n = bits_to_normal(x0 ^ x1);
            float hh = hv[c];
            hv[c] = fast_tanh(hh - (hh - pv[c]) * 0.1f + n * scale);
        }
    }

    float4 o4 = {hv[0], hv[1], hv[2], hv[3]};
    *(float4*)(out + base) = o4;
}

// ---------------------------------------------------------------------------
// Launch: 4-way M-pipelined schedule; steps on a HIGH-PRIORITY stream so the
// work distributor places their CTAs into retiring GEMM slots (they co-fit:
// 44K+12K regs, 192KB+0 smem per SM).
// ---------------------------------------------------------------------------
extern "C" void kernel_launch(void* const* d_in, const int* in_sizes, int n_in,
                              void* d_out, int out_size) {
    const float* h_init   = (const float*)d_in[0];
    const float* x_ctx    = (const float*)d_in[1];
    const float* surprise = (const float*)d_in[2];
    const float* weight   = (const float*)d_in[3];
    float* out = (float*)d_out;

    FoldedKeys keys;
    for (int i = 0; i < 5; i++) {
        uint32_t x0 = 0u, x1 = (uint32_t)i;
        threefry2x32(0u, 42u, x0, x1);
        keys.k[2 * i]     = x0;
        keys.k[2 * i + 1] = x1;
    }

    static cudaStream_t sG1 = nullptr, sG2 = nullptr, sS = nullptr;
    static cudaEvent_t ePre = nullptr, eJoin = nullptr;
    static cudaEvent_t eA[4] = {}, eG[4] = {};
    if (!sG1) {
        int lo, hi;
        cudaDeviceGetStreamPriorityRange(&lo, &hi);
        cudaStreamCreateWithFlags(&sG1, cudaStreamNonBlocking);
        cudaStreamCreateWithFlags(&sG2, cudaStreamNonBlocking);
        cudaStreamCreateWithPriority(&sS, cudaStreamNonBlocking, hi);
        cudaEventCreateWithFlags(&ePre, cudaEventDisableTiming);
        cudaEventCreateWithFlags(&eJoin, cudaEventDisableTiming);
        for (int q = 0; q < 4; q++) {
            cudaEventCreateWithFlags(&eA[q], cudaEventDisableTiming);
            cudaEventCreateWithFlags(&eG[q], cudaEventDisableTiming);
        }
    }

    cudaFuncSetAttribute(gemm_bf16x3, cudaFuncAttributeMaxDynamicSharedMemorySize, GEMM_SMEM);

    const size_t QE = (size_t)MQUART * DINNER;          // A elems per quarter
    const int    SPLITA_BLKS = (int)(QE / 1024);
    const dim3   GEMM_GRID(DSTATE / 128, MQUART / 128);
    const int    STEP_BLKS = (TOTAL / 4) / (256 * 4);
    const int    STEP_ELEMS = TOTAL / 4;

    // prologue on stream0
    reduce_noise_scale<<<1, 1024>>>(surprise);
    split_W<<<dim3(DSTATE / 32, DINNER / 64), 256>>>(weight);
    cudaEventRecord(ePre, 0);

    cudaStream_t gs[4] = {sG1, sG2, sG1, sG2};
    for (int q = 0; q < 4; q++) {
        // splitA quarter q on stream0 (overlaps earlier GEMM quarters)
        split_A<<<SPLITA_BLKS, 256>>>(x_ctx, QE * q);
        cudaEventRecord(eA[q], 0);

        // GEMM quarter q
        cudaStreamWaitEvent(gs[q], eA[q], 0);
        if (q < 2) cudaStreamWaitEvent(gs[q], ePre, 0);
        gemm_bf16x3<<<GEMM_GRID, 256, GEMM_SMEM, gs[q]>>>(MQUART * q);
        cudaEventRecord(eG[q], gs[q]);

        // step quarter q on high-priority stream (co-resides with later GEMMs)
        cudaStreamWaitEvent(sS, eG[q], 0);
        step_kernel<<<STEP_BLKS, 256, 0, sS>>>(h_init, out, keys, STEP_ELEMS * q);
    }

    // join side stream back to origin stream for capture correctness
    cudaEventRecord(eJoin, sS);
    cudaStreamWaitEvent(0, eJoin, 0);
}